// round 1
// baseline (speedup 1.0000x reference)
#include <cuda_runtime.h>
#include <cstdint>

#define BB 64
#define TT 2000
#define QD 1024
#define MD 512
#define AD 128
#define NF 32
#define KW 31

#define TTILE 128
#define KC 32
#define ASTR 36    // A smem stride: (36*r + c)%32 = (4r+c)%32 bijective over r0..7,c0..3
#define BSTR 136   // B smem stride: (136*k + n)%32 = (8k+n)%32 bijective over k0..3,n0..7

// scratch for processed query (no allocation allowed)
__device__ float g_pq[BB * AD];

__device__ __forceinline__ float fast_tanh(float x) {
    // accurate to ~1e-6 rel; 2 MUFU (ex2 + rcp)
    x = fminf(15.0f, fmaxf(-15.0f, x));
    float e = __expf(2.0f * x);
    return (e - 1.0f) * __frcp_rn(e + 1.0f);
}

__device__ __forceinline__ float to_tf32(float x) {
    unsigned r;
    asm("cvt.rna.tf32.f32 %0, %1;" : "=r"(r) : "f"(x));
    return __uint_as_float(r);
}

__device__ __forceinline__ void mma8(float& c0, float& c1, float& c2, float& c3,
                                     unsigned a0, unsigned a1, unsigned a2, unsigned a3,
                                     unsigned b0, unsigned b1) {
    asm volatile(
        "mma.sync.aligned.m16n8k8.row.col.f32.tf32.tf32.f32 "
        "{%0,%1,%2,%3}, {%4,%5,%6,%7}, {%8,%9}, {%0,%1,%2,%3};"
        : "+f"(c0), "+f"(c1), "+f"(c2), "+f"(c3)
        : "r"(a0), "r"(a1), "r"(a2), "r"(a3), "r"(b0), "r"(b1));
}

// ---------------- Kernel 1: pq = tanh(query @ Wq), and zero context region ----
__global__ void k_pq(const float* __restrict__ q, const float* __restrict__ Wq,
                     float* __restrict__ ctx) {
    __shared__ float qs[QD];
    int b = blockIdx.x;
    for (int i = threadIdx.x; i < QD; i += 128) qs[i] = q[b * QD + i];
    for (int i = threadIdx.x; i < MD; i += 128) ctx[b * MD + i] = 0.0f;
    __syncthreads();
    int a = threadIdx.x;
    float acc = 0.0f;
#pragma unroll 8
    for (int k = 0; k < QD; k++) acc += qs[k] * Wq[k * AD + a];
    g_pq[b * AD + a] = fast_tanh(acc);
}

// ---------------- Kernel 2: fused conv + loc GEMM + pm GEMM + energies --------
// grid: (16 t-tiles, 64 b), 512 threads (16 warps: 4 M-warps x 4 N-warps)
__global__ void __launch_bounds__(512, 1)
k_energies(const float* __restrict__ mem, const float* __restrict__ awc,
           const float* __restrict__ Wm, const float* __restrict__ ck,
           const float* __restrict__ Wloc, const float* __restrict__ Vv,
           float* __restrict__ ener) {
    extern __shared__ float sm[];
    float* As   = sm;              // 2 * 128*36  = 9216 floats
    float* Bs   = sm + 9216;       // 2 * 32*136  = 8704
    float* awcs = sm + 17920;      // 2 * 160     = 320
    float* pqs  = sm + 18240;      // 128
    float* Vs   = sm + 18368;      // 128
    float* ered = sm + 18496;      // 4 * 128     = 512   (total 19008 floats)

    const int b  = blockIdx.y;
    const int t0 = blockIdx.x * TTILE;
    const int tid = threadIdx.x;
    const int lane = tid & 31, w = tid >> 5;
    const int wm = w >> 2, wn = w & 3;
    const int g = lane >> 2, j = lane & 3;

    // ---- setup: pq, V, awc halo tile ----
    if (tid < AD) { pqs[tid] = g_pq[b * AD + tid]; Vs[tid] = Vv[tid]; }
    for (int i = tid; i < 2 * 160; i += 512) {
        int c = i / 160, tl = i % 160;
        int t = t0 - 15 + tl;
        awcs[i] = (t >= 0 && t < TT) ? awc[(b * 2 + c) * TT + t] : 0.0f;
    }
    __syncthreads();

    // ---- phase 1: conv -> As[0] (tf32), Wloc -> Bs[0] (tf32) ----
    for (int i = tid; i < TTILE * NF; i += 512) {
        int tl = i >> 5, f = i & 31;
        float acc = 0.0f;
#pragma unroll
        for (int k = 0; k < KW; k++) {
            acc += awcs[tl + k]       * ck[(k * 2 + 0) * NF + f];
            acc += awcs[160 + tl + k] * ck[(k * 2 + 1) * NF + f];
        }
        As[tl * ASTR + f] = to_tf32(acc);
    }
    for (int i = tid; i < NF * AD; i += 512) {
        int f = i >> 7, a = i & 127;
        Bs[f * BSTR + a] = to_tf32(Wloc[i]);
    }
    __syncthreads();

    // ---- phase 2: loc GEMM (K=32) into register frags ----
    float locf[2][4][4];
#pragma unroll
    for (int mt = 0; mt < 2; mt++)
#pragma unroll
        for (int nt = 0; nt < 4; nt++)
#pragma unroll
            for (int r = 0; r < 4; r++) locf[mt][nt][r] = 0.0f;

#pragma unroll
    for (int ks = 0; ks < 4; ks++) {
        unsigned af[2][4];
#pragma unroll
        for (int mt = 0; mt < 2; mt++) {
            int r0 = wm * 32 + mt * 16 + g;
            int c0 = ks * 8 + j;
            af[mt][0] = __float_as_uint(As[r0 * ASTR + c0]);
            af[mt][1] = __float_as_uint(As[(r0 + 8) * ASTR + c0]);
            af[mt][2] = __float_as_uint(As[r0 * ASTR + c0 + 4]);
            af[mt][3] = __float_as_uint(As[(r0 + 8) * ASTR + c0 + 4]);
        }
#pragma unroll
        for (int nt = 0; nt < 4; nt++) {
            int nb = wn * 32 + nt * 8;
            unsigned b0 = __float_as_uint(Bs[(ks * 8 + j) * BSTR + nb + g]);
            unsigned b1 = __float_as_uint(Bs[(ks * 8 + j + 4) * BSTR + nb + g]);
#pragma unroll
            for (int mt = 0; mt < 2; mt++)
                mma8(locf[mt][nt][0], locf[mt][nt][1], locf[mt][nt][2], locf[mt][nt][3],
                     af[mt][0], af[mt][1], af[mt][2], af[mt][3], b0, b1);
        }
    }
    // transform: locf := tanh(loc) + pq[col]
#pragma unroll
    for (int mt = 0; mt < 2; mt++)
#pragma unroll
        for (int nt = 0; nt < 4; nt++) {
            int col0 = wn * 32 + nt * 8 + 2 * j;
            float p0 = pqs[col0], p1 = pqs[col0 + 1];
            locf[mt][nt][0] = fast_tanh(locf[mt][nt][0]) + p0;
            locf[mt][nt][1] = fast_tanh(locf[mt][nt][1]) + p1;
            locf[mt][nt][2] = fast_tanh(locf[mt][nt][2]) + p0;
            locf[mt][nt][3] = fast_tanh(locf[mt][nt][3]) + p1;
        }
    __syncthreads();  // done with As[0]/Bs[0] before reuse as GEMM buffers

    // ---- phase 3: pm GEMM, K=512 in 16 chunks of 32, double-buffered ----
    // per-thread staging coordinates (2 float4 each for A and B)
    const int ar0 = tid >> 3,          ac0 = (tid & 7) * 4;
    const int ar1 = (tid + 512) >> 3,  ac1 = ((tid + 512) & 7) * 4;
    const int br0 = tid >> 5,          bc0 = (tid & 31) * 4;
    const int br1 = (tid + 512) >> 5,  bc1 = ((tid + 512) & 31) * 4;
    const bool av0 = (t0 + ar0) < TT;
    const bool av1 = (t0 + ar1) < TT;
    const float* pA0 = mem + ((size_t)(b * TT + t0 + ar0)) * MD + ac0;
    const float* pA1 = mem + ((size_t)(b * TT + t0 + ar1)) * MD + ac1;
    const float* pB0 = Wm + br0 * AD + bc0;
    const float* pB1 = Wm + br1 * AD + bc1;
    const int sa0 = ar0 * ASTR + ac0, sa1 = ar1 * ASTR + ac1;
    const int sb0 = br0 * BSTR + bc0, sb1 = br1 * BSTR + bc1;

    float acc[2][4][4];
#pragma unroll
    for (int mt = 0; mt < 2; mt++)
#pragma unroll
        for (int nt = 0; nt < 4; nt++)
#pragma unroll
            for (int r = 0; r < 4; r++) acc[mt][nt][r] = 0.0f;

    float4 ra0, ra1, rb0, rb1;
    const float4 z4 = make_float4(0.f, 0.f, 0.f, 0.f);

    // prologue: load+store chunk 0 into buffer 0
    ra0 = av0 ? *(const float4*)(pA0) : z4;
    ra1 = av1 ? *(const float4*)(pA1) : z4;
    rb0 = *(const float4*)(pB0);
    rb1 = *(const float4*)(pB1);
    {
        float4 v;
        v.x = to_tf32(ra0.x); v.y = to_tf32(ra0.y); v.z = to_tf32(ra0.z); v.w = to_tf32(ra0.w);
        *(float4*)&As[sa0] = v;
        v.x = to_tf32(ra1.x); v.y = to_tf32(ra1.y); v.z = to_tf32(ra1.z); v.w = to_tf32(ra1.w);
        *(float4*)&As[sa1] = v;
        v.x = to_tf32(rb0.x); v.y = to_tf32(rb0.y); v.z = to_tf32(rb0.z); v.w = to_tf32(rb0.w);
        *(float4*)&Bs[sb0] = v;
        v.x = to_tf32(rb1.x); v.y = to_tf32(rb1.y); v.z = to_tf32(rb1.z); v.w = to_tf32(rb1.w);
        *(float4*)&Bs[sb1] = v;
    }
    __syncthreads();

    for (int it = 0; it < 16; it++) {
        const int buf = it & 1;
        // prefetch next chunk to registers
        if (it < 15) {
            const int k0 = (it + 1) * KC;
            ra0 = av0 ? *(const float4*)(pA0 + k0) : z4;
            ra1 = av1 ? *(const float4*)(pA1 + k0) : z4;
            rb0 = *(const float4*)(pB0 + k0 * AD);
            rb1 = *(const float4*)(pB1 + k0 * AD);
        }
        // compute current chunk
        const float* Ab = As + buf * (TTILE * ASTR);
        const float* Bb = Bs + buf * (KC * BSTR);
#pragma unroll
        for (int ks = 0; ks < 4; ks++) {
            unsigned af[2][4];
#pragma unroll
            for (int mt = 0; mt < 2; mt++) {
                int r0 = wm * 32 + mt * 16 + g;
                int c0 = ks * 8 + j;
                af[mt][0] = __float_as_uint(Ab[r0 * ASTR + c0]);
                af[mt][1] = __float_as_uint(Ab[(r0 + 8) * ASTR + c0]);
                af[mt][2] = __float_as_uint(Ab[r0 * ASTR + c0 + 4]);
                af[mt][3] = __float_as_uint(Ab[(r0 + 8) * ASTR + c0 + 4]);
            }
#pragma unroll
            for (int nt = 0; nt < 4; nt++) {
                int nb = wn * 32 + nt * 8;
                unsigned b0 = __float_as_uint(Bb[(ks * 8 + j) * BSTR + nb + g]);
                unsigned b1 = __float_as_uint(Bb[(ks * 8 + j + 4) * BSTR + nb + g]);
#pragma unroll
                for (int mt = 0; mt < 2; mt++)
                    mma8(acc[mt][nt][0], acc[mt][nt][1], acc[mt][nt][2], acc[mt][nt][3],
                         af[mt][0], af[mt][1], af[mt][2], af[mt][3], b0, b1);
            }
        }
        // store prefetched chunk to the other buffer
        if (it < 15) {
            float* Aw = As + (1 - buf) * (TTILE * ASTR);
            float* Bw = Bs + (1 - buf) * (KC * BSTR);
            float4 v;
            v.x = to_tf32(ra0.x); v.y = to_tf32(ra0.y); v.z = to_tf32(ra0.z); v.w = to_tf32(ra0.w);
            *(float4*)&Aw[sa0] = v;
            v.x = to_tf32(ra1.x); v.y = to_tf32(ra1.y); v.z = to_tf32(ra1.z); v.w = to_tf32(ra1.w);
            *(float4*)&Aw[sa1] = v;
            v.x = to_tf32(rb0.x); v.y = to_tf32(rb0.y); v.z = to_tf32(rb0.z); v.w = to_tf32(rb0.w);
            *(float4*)&Bw[sb0] = v;
            v.x = to_tf32(rb1.x); v.y = to_tf32(rb1.y); v.z = to_tf32(rb1.z); v.w = to_tf32(rb1.w);
            *(float4*)&Bw[sb1] = v;
        }
        __syncthreads();
    }

    // ---- epilogue: e[t] = sum_a V[a] * tanh(pq + tanh(loc) + tanh(pm)) ----
#pragma unroll
    for (int mt = 0; mt < 2; mt++) {
        float p0 = 0.0f, p1 = 0.0f;  // rows g, g+8 of this m-tile
#pragma unroll
        for (int nt = 0; nt < 4; nt++) {
            int col0 = wn * 32 + nt * 8 + 2 * j;
            float v0 = Vs[col0], v1 = Vs[col0 + 1];
            p0 += v0 * fast_tanh(locf[mt][nt][0] + fast_tanh(acc[mt][nt][0]));
            p0 += v1 * fast_tanh(locf[mt][nt][1] + fast_tanh(acc[mt][nt][1]));
            p1 += v0 * fast_tanh(locf[mt][nt][2] + fast_tanh(acc[mt][nt][2]));
            p1 += v1 * fast_tanh(locf[mt][nt][3] + fast_tanh(acc[mt][nt][3]));
        }
        p0 += __shfl_xor_sync(0xffffffffu, p0, 1);
        p0 += __shfl_xor_sync(0xffffffffu, p0, 2);
        p1 += __shfl_xor_sync(0xffffffffu, p1, 1);
        p1 += __shfl_xor_sync(0xffffffffu, p1, 2);
        if (j == 0) {
            int r = wm * 32 + mt * 16 + g;
            ered[wn * 128 + r] = p0;
            ered[wn * 128 + r + 8] = p1;
        }
    }
    __syncthreads();
    if (tid < TTILE) {
        float e = ered[tid] + ered[128 + tid] + ered[256 + tid] + ered[384 + tid];
        int t = t0 + tid;
        if (t < TT) ener[b * TT + t] = e;
    }
}

// ---------------- Kernel 3: softmax over T per batch row ---------------------
__global__ void k_softmax(float* __restrict__ wts) {
    __shared__ float red[256];
    const int b = blockIdx.x, tid = threadIdx.x;
    float* e = wts + b * TT;
    float v[8];
    float mx = -1e30f;
#pragma unroll
    for (int i = 0; i < 8; i++) {
        int t = tid + i * 256;
        v[i] = (t < TT) ? e[t] : -1e30f;
        mx = fmaxf(mx, v[i]);
    }
    red[tid] = mx; __syncthreads();
    for (int s = 128; s > 0; s >>= 1) {
        if (tid < s) red[tid] = fmaxf(red[tid], red[tid + s]);
        __syncthreads();
    }
    mx = red[0]; __syncthreads();
    float sum = 0.0f;
#pragma unroll
    for (int i = 0; i < 8; i++) {
        int t = tid + i * 256;
        v[i] = (t < TT) ? __expf(v[i] - mx) : 0.0f;
        sum += v[i];
    }
    red[tid] = sum; __syncthreads();
    for (int s = 128; s > 0; s >>= 1) {
        if (tid < s) red[tid] += red[tid + s];
        __syncthreads();
    }
    float inv = 1.0f / red[0];
#pragma unroll
    for (int i = 0; i < 8; i++) {
        int t = tid + i * 256;
        if (t < TT) e[t] = v[i] * inv;
    }
}

// ---------------- Kernel 4: context = w @ memory (memory-bound) --------------
// grid: (8 t-chunks, 64 b), 256 threads. Each thread owns 2 d-columns.
__global__ void k_context(const float* __restrict__ mem, const float* __restrict__ wts,
                          float* __restrict__ ctx) {
    __shared__ float ws[250];
    const int b = blockIdx.y, tc = blockIdx.x, tid = threadIdx.x;
    const int tstart = tc * 250;
    if (tid < 250) ws[tid] = wts[b * TT + tstart + tid];
    __syncthreads();
    const int d = tid * 2;
    const float* mp = mem + ((size_t)b * TT + tstart) * MD + d;
    float a0 = 0.0f, a1 = 0.0f;
#pragma unroll 4
    for (int t = 0; t < 250; t++) {
        float2 m = *(const float2*)(mp + (size_t)t * MD);
        float wv = ws[t];
        a0 += wv * m.x;
        a1 += wv * m.y;
    }
    atomicAdd(&ctx[b * MD + d], a0);
    atomicAdd(&ctx[b * MD + d + 1], a1);
}

// ---------------- launch -----------------------------------------------------
extern "C" void kernel_launch(void* const* d_in, const int* in_sizes, int n_in,
                              void* d_out, int out_size) {
    const float* q    = (const float*)d_in[0];
    const float* mem  = (const float*)d_in[1];
    const float* awc  = (const float*)d_in[2];
    const float* Wq   = (const float*)d_in[3];
    const float* Wm   = (const float*)d_in[4];
    const float* ck   = (const float*)d_in[5];
    const float* Wloc = (const float*)d_in[6];
    const float* V    = (const float*)d_in[7];

    float* ctx = (float*)d_out;            // [64, 512]
    float* wts = (float*)d_out + BB * MD;  // [64, 2000] (energies -> softmax in place)

    cudaFuncSetAttribute(k_energies, cudaFuncAttributeMaxDynamicSharedMemorySize, 19008 * 4);

    k_pq<<<BB, 128>>>(q, Wq, ctx);
    dim3 gE(16, BB);
    k_energies<<<gE, 512, 19008 * 4>>>(mem, awc, Wm, ck, Wloc, V, wts);
    k_softmax<<<BB, 256>>>(wts);
    dim3 gC(8, BB);
    k_context<<<gC, 256>>>(mem, wts, ctx);
}